// round 1
// baseline (speedup 1.0000x reference)
#include <cuda_runtime.h>

#define CDIM 64
#define MAXN 100000

__device__ float g_q[MAXN * CDIM];
__device__ float g_k[MAXN * CDIM];
__device__ float g_v[MAXN * CDIM];
__device__ float g_acc[MAXN * CDIM * 2];   // [node][chan][{num, denom}]

__device__ __forceinline__ void red_add_v4(float* p, float a, float b, float c, float d) {
    asm volatile("red.global.add.v4.f32 [%0], {%1, %2, %3, %4};"
                 :: "l"(p), "f"(a), "f"(b), "f"(c), "f"(d) : "memory");
}

// ---------------------------------------------------------------------------
// Zero the accumulator
// ---------------------------------------------------------------------------
__global__ void k_zero(int n4) {
    int i = blockIdx.x * blockDim.x + threadIdx.x;
    if (i < n4) ((float4*)g_acc)[i] = make_float4(0.f, 0.f, 0.f, 0.f);
}

// ---------------------------------------------------------------------------
// Fused node preprocessing: h = LN(relu(x@W_in+b)); q=h@W_dst; k=h@W_src; v=h@W_lin
// warp-per-node, lane owns channels {2l, 2l+1}
// smem: W_in|W_dst|W_src|W_lin (4*4096) + b_in/ln_g/ln_b (192) + scratch (nw*128)
// ---------------------------------------------------------------------------
__global__ void k_node(int N, const float* __restrict__ x,
                       const float* __restrict__ W_in, const float* __restrict__ b_in,
                       const float* __restrict__ ln_g, const float* __restrict__ ln_b,
                       const float* __restrict__ W_lin, const float* __restrict__ W_src,
                       const float* __restrict__ W_dst) {
    extern __shared__ float sm[];
    float* sWin = sm;
    float* sWq  = sm + 4096;
    float* sWk  = sm + 8192;
    float* sWv  = sm + 12288;
    float* sP   = sm + 16384;          // b_in[64], ln_g[64], ln_b[64]
    float* sScr = sm + 16384 + 192;

    for (int i = threadIdx.x; i < 4096; i += blockDim.x) {
        sWin[i] = W_in[i]; sWq[i] = W_dst[i]; sWk[i] = W_src[i]; sWv[i] = W_lin[i];
    }
    if (threadIdx.x < 64) {
        sP[threadIdx.x]       = b_in[threadIdx.x];
        sP[64 + threadIdx.x]  = ln_g[threadIdx.x];
        sP[128 + threadIdx.x] = ln_b[threadIdx.x];
    }
    __syncthreads();

    const int warp = threadIdx.x >> 5, lane = threadIdx.x & 31;
    const int c0 = lane * 2;
    float* A = sScr + warp * 128;
    float* B = A + 64;
    const int gw = blockIdx.x * (blockDim.x >> 5) + warp;
    const int nw = gridDim.x * (blockDim.x >> 5);
    const float2* wIn = (const float2*)sWin;
    const float2* wQ  = (const float2*)sWq;
    const float2* wK  = (const float2*)sWk;
    const float2* wV  = (const float2*)sWv;

    for (int n = gw; n < N; n += nw) {
        float2 xv = *(const float2*)(x + (size_t)n * 64 + c0);
        A[c0] = xv.x; A[c0 + 1] = xv.y;
        __syncwarp();

        float ta = sP[c0], tb = sP[c0 + 1];
        #pragma unroll 16
        for (int h = 0; h < 64; h++) {
            float2 w = wIn[h * 32 + lane];
            float hv = A[h];
            ta = fmaf(hv, w.x, ta); tb = fmaf(hv, w.y, tb);
        }
        ta = fmaxf(ta, 0.f); tb = fmaxf(tb, 0.f);

        // LayerNorm over 64 channels (2 per lane)
        float s1 = ta + tb, s2 = ta * ta + tb * tb;
        #pragma unroll
        for (int o = 16; o > 0; o >>= 1) {
            s1 += __shfl_xor_sync(0xffffffffu, s1, o);
            s2 += __shfl_xor_sync(0xffffffffu, s2, o);
        }
        float mu  = s1 * 0.015625f;
        float var = s2 * 0.015625f - mu * mu;
        float inv = rsqrtf(var + 1e-5f);
        float ha = (ta - mu) * inv * sP[64 + c0]     + sP[128 + c0];
        float hb = (tb - mu) * inv * sP[64 + c0 + 1] + sP[128 + c0 + 1];
        B[c0] = ha; B[c0 + 1] = hb;
        __syncwarp();

        float qa = 0.f, qb = 0.f, ka = 0.f, kb = 0.f, va = 0.f, vb = 0.f;
        #pragma unroll 16
        for (int h = 0; h < 64; h++) {
            float hv = B[h];
            float2 w1 = wQ[h * 32 + lane];
            float2 w2 = wK[h * 32 + lane];
            float2 w3 = wV[h * 32 + lane];
            qa = fmaf(hv, w1.x, qa); qb = fmaf(hv, w1.y, qb);
            ka = fmaf(hv, w2.x, ka); kb = fmaf(hv, w2.y, kb);
            va = fmaf(hv, w3.x, va); vb = fmaf(hv, w3.y, vb);
        }
        *(float2*)(g_q + (size_t)n * 64 + c0) = make_float2(qa, qb);
        *(float2*)(g_k + (size_t)n * 64 + c0) = make_float2(ka, kb);
        *(float2*)(g_v + (size_t)n * 64 + c0) = make_float2(va, vb);
        __syncwarp();
    }
}

// ---------------------------------------------------------------------------
// Edge kernel: 2 edges per warp, single pass (no max-shift needed: alpha >= 0,
// inputs O(1) => exp cannot overflow; softmax ratio is shift-invariant).
// Per edge: delta = mlp2(pos[d]-pos[s]); alpha = mlp2(q[d]-k[s]+delta);
// e = exp(alpha); red {e*(v[s]+delta), e} into g_acc[d].
// smem: pnW1(192)|pnW2(4096)|anW1(4096)|anW2(4096)|biases(256)|scratch(nw*256)
// ---------------------------------------------------------------------------
__global__ void k_edge(int E, const int* __restrict__ ei, const float* __restrict__ pos,
                       const float* __restrict__ pnW1, const float* __restrict__ pnb1,
                       const float* __restrict__ pnW2, const float* __restrict__ pnb2,
                       const float* __restrict__ anW1, const float* __restrict__ anb1,
                       const float* __restrict__ anW2, const float* __restrict__ anb2) {
    extern __shared__ float sm[];
    float* sPnW1 = sm;                   // 192
    float* sPnW2 = sm + 192;             // 4096
    float* sAnW1 = sm + 192 + 4096;      // 4096
    float* sAnW2 = sm + 192 + 8192;      // 4096
    float* sBias = sm + 192 + 12288;     // pnb1|pnb2|anb1|anb2 (4*64)
    float* sScr  = sBias + 256;          // nwarps * 256

    for (int i = threadIdx.x; i < 192; i += blockDim.x) sPnW1[i] = pnW1[i];
    for (int i = threadIdx.x; i < 4096; i += blockDim.x) {
        sPnW2[i] = pnW2[i]; sAnW1[i] = anW1[i]; sAnW2[i] = anW2[i];
    }
    if (threadIdx.x < 64) {
        sBias[threadIdx.x]       = pnb1[threadIdx.x];
        sBias[64 + threadIdx.x]  = pnb2[threadIdx.x];
        sBias[128 + threadIdx.x] = anb1[threadIdx.x];
        sBias[192 + threadIdx.x] = anb2[threadIdx.x];
    }
    __syncthreads();

    const int warp = threadIdx.x >> 5, lane = threadIdx.x & 31;
    const int c0 = lane * 2;
    float* A0 = sScr + warp * 256;
    float* B0 = A0 + 64;
    float* A1 = B0 + 64;
    float* B1 = A1 + 64;
    const int gw = blockIdx.x * (blockDim.x >> 5) + warp;
    const int nw = gridDim.x * (blockDim.x >> 5);
    const float2* W1p = (const float2*)sPnW1;
    const float2* W2p = (const float2*)sPnW2;
    const float2* W1a = (const float2*)sAnW1;
    const float2* W2a = (const float2*)sAnW2;

    for (int e0 = gw * 2; e0 < E; e0 += nw * 2) {
        const int e1 = e0 + 1;
        const bool has1 = (e1 < E);
        const int s0 = ei[e0],               d0 = ei[E + e0];
        const int s1 = has1 ? ei[e1] : s0;
        const int d1 = has1 ? ei[E + e1] : d0;

        float p00 = pos[d0*3+0] - pos[s0*3+0];
        float p01 = pos[d0*3+1] - pos[s0*3+1];
        float p02 = pos[d0*3+2] - pos[s0*3+2];
        float p10 = pos[d1*3+0] - pos[s1*3+0];
        float p11 = pos[d1*3+1] - pos[s1*3+1];
        float p12 = pos[d1*3+2] - pos[s1*3+2];

        // pos MLP layer 1 (3 -> 64)
        float2 w0 = W1p[lane], w1 = W1p[32 + lane], w2 = W1p[64 + lane];
        float b1a = sBias[c0], b1b = sBias[c0 + 1];
        float h0a = fmaf(p02, w2.x, fmaf(p01, w1.x, fmaf(p00, w0.x, b1a)));
        float h0b = fmaf(p02, w2.y, fmaf(p01, w1.y, fmaf(p00, w0.y, b1b)));
        float h1a = fmaf(p12, w2.x, fmaf(p11, w1.x, fmaf(p10, w0.x, b1a)));
        float h1b = fmaf(p12, w2.y, fmaf(p11, w1.y, fmaf(p10, w0.y, b1b)));
        A0[c0] = fmaxf(h0a, 0.f); A0[c0 + 1] = fmaxf(h0b, 0.f);
        A1[c0] = fmaxf(h1a, 0.f); A1[c0 + 1] = fmaxf(h1b, 0.f);
        __syncwarp();

        // pos MLP layer 2 (64 -> 64) -> delta (kept in regs, relu'd)
        float dl0a = sBias[64 + c0], dl0b = sBias[64 + c0 + 1];
        float dl1a = dl0a, dl1b = dl0b;
        #pragma unroll 16
        for (int h = 0; h < 64; h++) {
            float2 w = W2p[h * 32 + lane];
            float v0 = A0[h], v1 = A1[h];
            dl0a = fmaf(v0, w.x, dl0a); dl0b = fmaf(v0, w.y, dl0b);
            dl1a = fmaf(v1, w.x, dl1a); dl1b = fmaf(v1, w.y, dl1b);
        }
        dl0a = fmaxf(dl0a, 0.f); dl0b = fmaxf(dl0b, 0.f);
        dl1a = fmaxf(dl1a, 0.f); dl1b = fmaxf(dl1b, 0.f);

        // attention input: q[d] - k[s] + delta
        float2 q0 = *(const float2*)(g_q + (size_t)d0 * 64 + c0);
        float2 k0 = *(const float2*)(g_k + (size_t)s0 * 64 + c0);
        float2 q1 = *(const float2*)(g_q + (size_t)d1 * 64 + c0);
        float2 k1 = *(const float2*)(g_k + (size_t)s1 * 64 + c0);
        B0[c0] = q0.x - k0.x + dl0a; B0[c0 + 1] = q0.y - k0.y + dl0b;
        B1[c0] = q1.x - k1.x + dl1a; B1[c0 + 1] = q1.y - k1.y + dl1b;
        __syncwarp();

        // attn MLP layer 1 (64 -> 64)
        float g0a = sBias[128 + c0], g0b = sBias[128 + c0 + 1];
        float g1a = g0a, g1b = g0b;
        #pragma unroll 16
        for (int h = 0; h < 64; h++) {
            float2 w = W1a[h * 32 + lane];
            float v0 = B0[h], v1 = B1[h];
            g0a = fmaf(v0, w.x, g0a); g0b = fmaf(v0, w.y, g0b);
            g1a = fmaf(v1, w.x, g1a); g1b = fmaf(v1, w.y, g1b);
        }
        A0[c0] = fmaxf(g0a, 0.f); A0[c0 + 1] = fmaxf(g0b, 0.f);
        A1[c0] = fmaxf(g1a, 0.f); A1[c0 + 1] = fmaxf(g1b, 0.f);
        __syncwarp();

        // attn MLP layer 2 (64 -> 64) -> alpha -> e = exp(alpha)
        float a0a = sBias[192 + c0], a0b = sBias[192 + c0 + 1];
        float a1a = a0a, a1b = a0b;
        #pragma unroll 16
        for (int h = 0; h < 64; h++) {
            float2 w = W2a[h * 32 + lane];
            float v0 = A0[h], v1 = A1[h];
            a0a = fmaf(v0, w.x, a0a); a0b = fmaf(v0, w.y, a0b);
            a1a = fmaf(v1, w.x, a1a); a1b = fmaf(v1, w.y, a1b);
        }
        float ex0a = __expf(fmaxf(a0a, 0.f));
        float ex0b = __expf(fmaxf(a0b, 0.f));
        float ex1a = __expf(fmaxf(a1a, 0.f));
        float ex1b = __expf(fmaxf(a1b, 0.f));

        float2 vv0 = *(const float2*)(g_v + (size_t)s0 * 64 + c0);
        red_add_v4(g_acc + (size_t)d0 * 128 + lane * 4,
                   ex0a * (vv0.x + dl0a), ex0a,
                   ex0b * (vv0.y + dl0b), ex0b);
        if (has1) {
            float2 vv1 = *(const float2*)(g_v + (size_t)s1 * 64 + c0);
            red_add_v4(g_acc + (size_t)d1 * 128 + lane * 4,
                       ex1a * (vv1.x + dl1a), ex1a,
                       ex1b * (vv1.y + dl1b), ex1b);
        }
        __syncwarp();   // protect A0/A1 (alpha reads) before next iter's h1 writes
    }
}

// ---------------------------------------------------------------------------
// Output: out = relu((num / (den + 1e-16)) @ W_out + b_out)
// ---------------------------------------------------------------------------
__global__ void k_out(int N, const float* __restrict__ W_out, const float* __restrict__ b_out,
                      float* __restrict__ out) {
    extern __shared__ float sm[];
    float* sW   = sm;           // 4096
    float* sb   = sm + 4096;    // 64
    float* sScr = sm + 4160;    // nwarps * 64

    for (int i = threadIdx.x; i < 4096; i += blockDim.x) sW[i] = W_out[i];
    if (threadIdx.x < 64) sb[threadIdx.x] = b_out[threadIdx.x];
    __syncthreads();

    const int warp = threadIdx.x >> 5, lane = threadIdx.x & 31;
    const int c0 = lane * 2;
    float* A = sScr + warp * 64;
    const int gw = blockIdx.x * (blockDim.x >> 5) + warp;
    const int nw = gridDim.x * (blockDim.x >> 5);
    const float2* wO = (const float2*)sW;

    for (int n = gw; n < N; n += nw) {
        float4 ld = *(const float4*)(g_acc + (size_t)n * 128 + lane * 4);
        A[c0]     = ld.x / (ld.y + 1e-16f);
        A[c0 + 1] = ld.z / (ld.w + 1e-16f);
        __syncwarp();
        float oa = sb[c0], ob = sb[c0 + 1];
        #pragma unroll 16
        for (int h = 0; h < 64; h++) {
            float2 w = wO[h * 32 + lane];
            float hv = A[h];
            oa = fmaf(hv, w.x, oa); ob = fmaf(hv, w.y, ob);
        }
        *(float2*)(out + (size_t)n * 64 + c0) = make_float2(fmaxf(oa, 0.f), fmaxf(ob, 0.f));
        __syncwarp();
    }
}

// ---------------------------------------------------------------------------

#define NODE_SMEM ((16384 + 192 + 8 * 128) * 4)       // 70400 B
#define EDGE_SMEM ((192 + 12288 + 256 + 8 * 256) * 4) // 59136 B
#define OUT_SMEM  ((4096 + 64 + 8 * 64) * 4)          // 18688 B

extern "C" void kernel_launch(void* const* d_in, const int* in_sizes, int n_in,
                              void* d_out, int out_size) {
    const float* x     = (const float*)d_in[0];
    const float* pos   = (const float*)d_in[1];
    const int*   ei    = (const int*)d_in[2];
    const float* W_in  = (const float*)d_in[3];
    const float* b_in  = (const float*)d_in[4];
    const float* ln_g  = (const float*)d_in[5];
    const float* ln_b  = (const float*)d_in[6];
    const float* W_lin = (const float*)d_in[7];
    const float* W_src = (const float*)d_in[8];
    const float* W_dst = (const float*)d_in[9];
    const float* pnW1  = (const float*)d_in[10];
    const float* pnb1  = (const float*)d_in[11];
    const float* pnW2  = (const float*)d_in[12];
    const float* pnb2  = (const float*)d_in[13];
    const float* anW1  = (const float*)d_in[14];
    const float* anb1  = (const float*)d_in[15];
    const float* anW2  = (const float*)d_in[16];
    const float* anb2  = (const float*)d_in[17];
    const float* W_out = (const float*)d_in[18];
    const float* b_out = (const float*)d_in[19];

    const int N = in_sizes[0] / 64;
    const int E = in_sizes[2] / 2;

    cudaFuncSetAttribute(k_node, cudaFuncAttributeMaxDynamicSharedMemorySize, NODE_SMEM);
    cudaFuncSetAttribute(k_edge, cudaFuncAttributeMaxDynamicSharedMemorySize, EDGE_SMEM);

    const int n4 = N * 32;  // N*128 floats / 4
    k_zero<<<(n4 + 255) / 256, 256>>>(n4);
    k_node<<<444, 256, NODE_SMEM>>>(N, x, W_in, b_in, ln_g, ln_b, W_lin, W_src, W_dst);
    k_edge<<<444, 256, EDGE_SMEM>>>(E, ei, pos, pnW1, pnb1, pnW2, pnb2,
                                    anW1, anb1, anW2, anb2);
    k_out<<<592, 256, OUT_SMEM>>>(N, W_out, b_out, (float*)d_out);
}